// round 9
// baseline (speedup 1.0000x reference)
#include <cuda_runtime.h>
#include <cuda_bf16.h>
#include <mma.h>
#include <math.h>

using namespace nvcuda;

#define NB    4
#define SS    128
#define CDIM  256
#define NHH   4
#define DHH   32
#define NWIN  256
#define WSZ   64
#define MTOT  (NB*SS*SS)
#define NQKV  768
#define QSCALE 0.17677669529663687f

typedef unsigned long long ull;

// ---------------- scratch ----------------
__device__ float g_q  [MTOT * CDIM];
__device__ float g_kv [MTOT * 2 * CDIM];
__device__ __nv_bfloat16 g_xhi[MTOT * CDIM];
__device__ __nv_bfloat16 g_xlo[MTOT * CDIM];
__device__ __nv_bfloat16 g_ahi[MTOT * CDIM];
__device__ __nv_bfloat16 g_alo[MTOT * CDIM];
__device__ __nv_bfloat16 g_whi[CDIM * NQKV];
__device__ __nv_bfloat16 g_wlo[CDIM * NQKV];
__device__ __nv_bfloat16 g_wohi[CDIM * CDIM];
__device__ __nv_bfloat16 g_wolo[CDIM * CDIM];
__device__ float g_pos1t[NHH * WSZ * WSZ];

// ---------------- helpers (no braces inside asm strings) ----------------
union F2U {
    float2 f;
    ull u;
};
__device__ __forceinline__ ull f2pack(float x, float y) {
    F2U t; t.f = make_float2(x, y); return t.u;
}
__device__ __forceinline__ float2 f2unpack(ull v) {
    F2U t; t.u = v; return t.f;
}
__device__ __forceinline__ ull ffma2(ull a, ull b, ull c) {
    ull d;
    asm("fma.rn.f32x2 %0,%1,%2,%3;" : "=l"(d) : "l"(a), "l"(b), "l"(c));
    return d;
}
__device__ __forceinline__ ull fmul2(ull a, ull b) {
    ull d;
    asm("mul.rn.f32x2 %0,%1,%2;" : "=l"(d) : "l"(a), "l"(b));
    return d;
}
__device__ __forceinline__ void split1(float x, __nv_bfloat16& h, __nv_bfloat16& l) {
    h = __float2bfloat16(x);
    l = __float2bfloat16(x - __bfloat162float(h));
}
__device__ __forceinline__ void cpasync16(void* s, const void* g) {
    unsigned saddr = (unsigned)__cvta_generic_to_shared(s);
    asm volatile("cp.async.cg.shared.global [%0], [%1], 16;" :: "r"(saddr), "l"(g));
}
__device__ __forceinline__ void cpcommit() {
    asm volatile("cp.async.commit_group;");
}
__device__ __forceinline__ void cpwait0() {
    asm volatile("cp.async.wait_group 0;");
}
__device__ __forceinline__ void cpwait1() {
    asm volatile("cp.async.wait_group 1;");
}

// ---------------- merged prep: pos1 transpose + weight splits ----------------
__global__ void prep_kernel(const float* __restrict__ p1,
                            const float* __restrict__ Wq,
                            const float* __restrict__ Wkv,
                            const float* __restrict__ Wo) {
    int idx = blockIdx.x * blockDim.x + threadIdx.x;
    int stride = gridDim.x * blockDim.x;
    for (int i = idx; i < NHH * WSZ * WSZ; i += stride) {
        int hh = i / (WSZ * WSZ);
        int rem = i - hh * WSZ * WSZ;
        int r = rem / WSZ;
        int c = rem % WSZ;
        g_pos1t[(hh * WSZ + c) * WSZ + r] = p1[i];
    }
    for (int i = idx; i < CDIM * CDIM; i += stride) {
        split1(Wo[i], g_wohi[i], g_wolo[i]);
    }
    for (int i = idx; i < CDIM * NQKV; i += stride) {
        int k = i / NQKV;
        int c = i % NQKV;
        float v = (c < 256) ? Wq[k * 256 + c] : Wkv[k * 512 + (c - 256)];
        split1(v, g_whi[i], g_wlo[i]);
    }
}

// ---------------- x split ----------------
__global__ void split_x(const float* __restrict__ src) {
    int idx = blockIdx.x * blockDim.x + threadIdx.x;
    int stride = gridDim.x * blockDim.x;
    const int n4 = MTOT * CDIM / 4;
    for (int i = idx; i < n4; i += stride) {
        float4 v = ((const float4*)src)[i];
        __nv_bfloat16 h4[4];
        __nv_bfloat16 l4[4];
        split1(v.x, h4[0], l4[0]);
        split1(v.y, h4[1], l4[1]);
        split1(v.z, h4[2], l4[2]);
        split1(v.w, h4[3], l4[3]);
        ((uint2*)g_xhi)[i] = *(uint2*)h4;
        ((uint2*)g_xlo)[i] = *(uint2*)l4;
    }
}

// ---------------- WMMA split-bf16 GEMM, cp.async double-buffered ------------
__device__ __forceinline__ int remap_row(int row) {
    int b = row >> 14;
    int n = (row >> 6) & 255;
    int m = row & 63;
    int h = ((n >> 4) << 3) + (m >> 3);
    int w = ((n & 15) << 3) + (m & 7);
    return (b << 14) + (h << 7) + w;
}

__global__ __launch_bounds__(256) void gemm_wmma(
    int mode, float* __restrict__ outp, const float* __restrict__ bo)
{
    const int Ntot = mode ? 256 : NQKV;
    const __nv_bfloat16* __restrict__ Ahi = mode ? g_ahi : g_xhi;
    const __nv_bfloat16* __restrict__ Alo = mode ? g_alo : g_xlo;
    const __nv_bfloat16* __restrict__ Bhi = mode ? g_wohi : g_whi;
    const __nv_bfloat16* __restrict__ Blo = mode ? g_wolo : g_wlo;

    __shared__ __align__(32) __nv_bfloat16 As[2][2][128][24];
    __shared__ __align__(32) __nv_bfloat16 Bs[2][2][16][136];

    const int tid = threadIdx.x;
    const int wid = tid >> 5;
    const int lane = tid & 31;
    const int nb0 = blockIdx.x * 128;
    const int mrow0 = blockIdx.y * 128;
    const int m0w = (wid & 3) * 32;
    const int n0w = (wid >> 2) * 64;

    wmma::fragment<wmma::accumulator, 16, 16, 16, float> cfrag[2][4];
#pragma unroll
    for (int mi = 0; mi < 2; mi++) {
#pragma unroll
        for (int ni = 0; ni < 4; ni++) {
            wmma::fill_fragment(cfrag[mi][ni], 0.0f);
        }
    }

    const int arow = tid >> 1;
    const int acol8 = (tid & 1) * 8;
    const int bkr = tid >> 4;
    const int bnc8 = (tid & 15) * 8;

    {
        cpasync16(&As[0][0][arow][acol8],
                  Ahi + (size_t)(mrow0 + arow) * 256 + acol8);
        cpasync16(&As[0][1][arow][acol8],
                  Alo + (size_t)(mrow0 + arow) * 256 + acol8);
        cpasync16(&Bs[0][0][bkr][bnc8],
                  Bhi + (size_t)(bkr) * Ntot + nb0 + bnc8);
        cpasync16(&Bs[0][1][bkr][bnc8],
                  Blo + (size_t)(bkr) * Ntot + nb0 + bnc8);
        cpcommit();
    }

    const int NT = 256 / 16;
    for (int t = 0; t < NT; t++) {
        int buf = t & 1;
        if (t + 1 < NT) {
            int kn = (t + 1) * 16;
            cpasync16(&As[1 - buf][0][arow][acol8],
                      Ahi + (size_t)(mrow0 + arow) * 256 + kn + acol8);
            cpasync16(&As[1 - buf][1][arow][acol8],
                      Alo + (size_t)(mrow0 + arow) * 256 + kn + acol8);
            cpasync16(&Bs[1 - buf][0][bkr][bnc8],
                      Bhi + (size_t)(kn + bkr) * Ntot + nb0 + bnc8);
            cpasync16(&Bs[1 - buf][1][bkr][bnc8],
                      Blo + (size_t)(kn + bkr) * Ntot + nb0 + bnc8);
            cpcommit();
            cpwait1();
        } else {
            cpwait0();
        }
        __syncthreads();

        wmma::fragment<wmma::matrix_a, 16, 16, 16, __nv_bfloat16, wmma::row_major> afh[2];
        wmma::fragment<wmma::matrix_a, 16, 16, 16, __nv_bfloat16, wmma::row_major> afl[2];
        wmma::load_matrix_sync(afh[0], &As[buf][0][m0w][0], 24);
        wmma::load_matrix_sync(afh[1], &As[buf][0][m0w + 16][0], 24);
        wmma::load_matrix_sync(afl[0], &As[buf][1][m0w][0], 24);
        wmma::load_matrix_sync(afl[1], &As[buf][1][m0w + 16][0], 24);
#pragma unroll
        for (int ni = 0; ni < 4; ni++) {
            wmma::fragment<wmma::matrix_b, 16, 16, 16, __nv_bfloat16, wmma::row_major> bfh;
            wmma::fragment<wmma::matrix_b, 16, 16, 16, __nv_bfloat16, wmma::row_major> bfl;
            wmma::load_matrix_sync(bfh, &Bs[buf][0][0][n0w + ni * 16], 136);
            wmma::load_matrix_sync(bfl, &Bs[buf][1][0][n0w + ni * 16], 136);
#pragma unroll
            for (int mi = 0; mi < 2; mi++) {
                wmma::mma_sync(cfrag[mi][ni], afh[mi], bfh, cfrag[mi][ni]);
                wmma::mma_sync(cfrag[mi][ni], afh[mi], bfl, cfrag[mi][ni]);
                wmma::mma_sync(cfrag[mi][ni], afl[mi], bfh, cfrag[mi][ni]);
            }
        }
        __syncthreads();
    }

    if (mode == 0) {
#pragma unroll
        for (int mi = 0; mi < 2; mi++) {
#pragma unroll
            for (int ni = 0; ni < 4; ni++) {
                int row = mrow0 + m0w + mi * 16;
                int col = nb0 + n0w + ni * 16;
                if (col < 256) {
#pragma unroll
                    for (int e = 0; e < cfrag[mi][ni].num_elements; e++) {
                        cfrag[mi][ni].x[e] *= QSCALE;
                    }
                    wmma::store_matrix_sync(g_q + (size_t)row * 256 + col,
                                            cfrag[mi][ni], 256, wmma::mem_row_major);
                } else {
                    wmma::store_matrix_sync(g_kv + (size_t)row * 512 + (col - 256),
                                            cfrag[mi][ni], 512, wmma::mem_row_major);
                }
            }
        }
    } else {
        float* stg = (float*)&As[0][0][0][0];
        float* mystg = stg + wid * 256;
#pragma unroll
        for (int mi = 0; mi < 2; mi++) {
#pragma unroll
            for (int ni = 0; ni < 4; ni++) {
                wmma::store_matrix_sync(mystg, cfrag[mi][ni], 16, wmma::mem_row_major);
                __syncwarp();
                int row0 = mrow0 + m0w + mi * 16;
                int col0 = nb0 + n0w + ni * 16;
#pragma unroll
                for (int e = 0; e < 8; e++) {
                    int idx = lane * 8 + e;
                    int r = idx >> 4;
                    int c = idx & 15;
                    int grow = remap_row(row0 + r);
                    outp[(size_t)grow * 256 + col0 + c] = mystg[r * 16 + c] + bo[col0 + c];
                }
                __syncwarp();
            }
        }
    }
}

// ---------------- attention branch 1 (within-window, seq=64) ----------------
__global__ __launch_bounds__(64) void attn1_kernel() {
    int n  = blockIdx.x;
    int hh = blockIdx.y;
    int b  = blockIdx.z;
    int i  = threadIdx.x;

    __shared__ float ks[WSZ][36];
    __shared__ float vs[WSZ][36];

    int h = ((n >> 4) << 3) + (i >> 3);
    int w = ((n & 15) << 3) + (i & 7);
    size_t grow = ((size_t)b << 14) + (h << 7) + w;

    {
        const float4* kp = (const float4*)(g_kv + grow * 512 + hh * DHH);
        const float4* vp = (const float4*)(g_kv + grow * 512 + 256 + hh * DHH);
#pragma unroll
        for (int d4 = 0; d4 < 8; d4++) {
            *(float4*)(&ks[i][d4 * 4]) = kp[d4];
            *(float4*)(&vs[i][d4 * 4]) = vp[d4];
        }
    }
    ull qr2[16];
    {
        const ulonglong2* qp = (const ulonglong2*)(g_q + grow * 256 + hh * DHH);
#pragma unroll
        for (int d4 = 0; d4 < 8; d4++) {
            ulonglong2 q4 = qp[d4];
            qr2[2 * d4]     = q4.x;
            qr2[2 * d4 + 1] = q4.y;
        }
    }
    __syncthreads();

    const float* pos = g_pos1t + hh * WSZ * WSZ;
    float mrun = -INFINITY;
    float l = 0.f;
    ull acc2[16];
#pragma unroll
    for (int t = 0; t < 16; t++) acc2[t] = 0ULL;

#pragma unroll 2
    for (int j = 0; j < WSZ; j++) {
        float pb = pos[j * WSZ + i];
        const ulonglong2* kp2 = (const ulonglong2*)(&ks[j][0]);
        ull sA = 0ULL;
        ull sB = 0ULL;
        ull sC = 0ULL;
        ull sD = 0ULL;
#pragma unroll
        for (int t = 0; t < 4; t++) {
            ulonglong2 k0 = kp2[t];
            ulonglong2 k1 = kp2[t + 4];
            sA = ffma2(qr2[2 * t],     k0.x, sA);
            sB = ffma2(qr2[2 * t + 1], k0.y, sB);
            sC = ffma2(qr2[2 * t + 8], k1.x, sC);
            sD = ffma2(qr2[2 * t + 9], k1.y, sD);
        }
        float2 a = f2unpack(sA);
        float2 bb = f2unpack(sB);
        float2 cc = f2unpack(sC);
        float2 dd = f2unpack(sD);
        float s = ((a.x + a.y) + (bb.x + bb.y)) + ((cc.x + cc.y) + (dd.x + dd.y)) + pb;
        if (s > mrun) {
            float c = __expf(mrun - s);
            mrun = s;
            l *= c;
            ull cc2 = f2pack(c, c);
#pragma unroll
            for (int t = 0; t < 16; t++) acc2[t] = fmul2(acc2[t], cc2);
        }
        float p = __expf(s - mrun);
        l += p;
        ull pp2 = f2pack(p, p);
        const ulonglong2* vp2 = (const ulonglong2*)(&vs[j][0]);
#pragma unroll
        for (int t = 0; t < 8; t++) {
            ulonglong2 vv = vp2[t];
            acc2[2 * t]     = ffma2(pp2, vv.x, acc2[2 * t]);
            acc2[2 * t + 1] = ffma2(pp2, vv.y, acc2[2 * t + 1]);
        }
    }
    float inv = 1.f / l;
    size_t obase = (((size_t)(b * NWIN + n) * WSZ) + i) * CDIM + hh * DHH;
#pragma unroll
    for (int t = 0; t < 8; t++) {
        float2 p0 = f2unpack(acc2[2 * t]);
        float2 p1 = f2unpack(acc2[2 * t + 1]);
        __nv_bfloat16 h4[4];
        __nv_bfloat16 l4[4];
        split1(p0.x * inv, h4[0], l4[0]);
        split1(p0.y * inv, h4[1], l4[1]);
        split1(p1.x * inv, h4[2], l4[2]);
        split1(p1.y * inv, h4[3], l4[3]);
        *(uint2*)(g_ahi + obase + t * 4) = *(uint2*)h4;
        *(uint2*)(g_alo + obase + t * 4) = *(uint2*)l4;
    }
}

// ---------------- attention branch 2 : WMMA tensor-core version -------------
// Block = (m, query-quarter qq, hh, b). 64 queries x 256 keys, dh=32.
// Smem layout (bytes):
#define TC_QHI 0
#define TC_QLO 5120
#define TC_KHI 10240
#define TC_KLO 30720
#define TC_VHI 51200
#define TC_VLO 71680
#define TC_S   92160
#define TC_PHI 158720
#define TC_PLO 192512
#define TC_LNV 226304
#define TC_SMEM 226560

__global__ __launch_bounds__(256) void attn2_tc(const float* __restrict__ p2) {
    const int mq = blockIdx.x;
    const int m  = mq >> 2;
    const int qq = mq & 3;
    const int hh = blockIdx.y;
    const int b  = blockIdx.z;
    const int tid = threadIdx.x;
    const int w = tid >> 5;
    const int lane = tid & 31;

    extern __shared__ char smc[];
    __nv_bfloat16* qhi = (__nv_bfloat16*)(smc + TC_QHI);
    __nv_bfloat16* qlo = (__nv_bfloat16*)(smc + TC_QLO);
    __nv_bfloat16* khi = (__nv_bfloat16*)(smc + TC_KHI);
    __nv_bfloat16* klo = (__nv_bfloat16*)(smc + TC_KLO);
    __nv_bfloat16* vhi = (__nv_bfloat16*)(smc + TC_VHI);
    __nv_bfloat16* vlo = (__nv_bfloat16*)(smc + TC_VLO);
    float* Sb  = (float*)(smc + TC_S);
    __nv_bfloat16* phi = (__nv_bfloat16*)(smc + TC_PHI);
    __nv_bfloat16* plo = (__nv_bfloat16*)(smc + TC_PLO);
    float* linv = (float*)(smc + TC_LNV);

    // ---- Phase A: load fp32, split to bf16 hi/lo ----
    for (int idx = tid; idx < 64 * 32; idx += 256) {
        int r = idx >> 5;
        int d = idx & 31;
        int i = qq * 64 + r;
        int h = ((i >> 4) << 3) + (m >> 3);
        int ww = ((i & 15) << 3) + (m & 7);
        size_t grow = ((size_t)b << 14) + (h << 7) + ww;
        float v = g_q[grow * 256 + 128 + hh * 32 + d];   // pre-scaled by QSCALE
        __nv_bfloat16 hi;
        __nv_bfloat16 lo;
        split1(v, hi, lo);
        qhi[r * 40 + d] = hi;
        qlo[r * 40 + d] = lo;
    }
    for (int idx = tid; idx < 256 * 32; idx += 256) {
        int r = idx >> 5;
        int d = idx & 31;
        int h = ((r >> 4) << 3) + (m >> 3);
        int ww = ((r & 15) << 3) + (m & 7);
        size_t gk = ((size_t)b << 14) + (h << 7) + ww;
        float kv = g_kv[gk * 512 + 128 + hh * 32 + d];
        float vv = g_kv[gk * 512 + 384 + hh * 32 + d];
        __nv_bfloat16 hi;
        __nv_bfloat16 lo;
        split1(kv, hi, lo);
        khi[r * 40 + d] = hi;
        klo[r * 40 + d] = lo;
        split1(vv, hi, lo);
        vhi[r * 40 + d] = hi;
        vlo[r * 40 + d] = lo;
    }
    __syncthreads();

    // ---- Phase B: S = Q @ K^T (3-term split), fp32 into smem ----
#pragma unroll
    for (int it = 0; it < 4; it++) {
        wmma::fragment<wmma::matrix_a, 16, 16, 16, __nv_bfloat16, wmma::row_major> ah[2];
        wmma::fragment<wmma::matrix_a, 16, 16, 16, __nv_bfloat16, wmma::row_major> al[2];
#pragma unroll
        for (int ks = 0; ks < 2; ks++) {
            wmma::load_matrix_sync(ah[ks], qhi + it * 16 * 40 + ks * 16, 40);
            wmma::load_matrix_sync(al[ks], qlo + it * 16 * 40 + ks * 16, 40);
        }
#pragma unroll
        for (int jj = 0; jj < 2; jj++) {
            int jt = w * 2 + jj;
            wmma::fragment<wmma::accumulator, 16, 16, 16, float> c;
            wmma::fill_fragment(c, 0.0f);
#pragma unroll
            for (int ks = 0; ks < 2; ks++) {
                wmma::fragment<wmma::matrix_b, 16, 16, 16, __nv_bfloat16, wmma::col_major> bh;
                wmma::fragment<wmma::matrix_b, 16, 16, 16, __nv_bfloat16, wmma::col_major> bl;
                wmma::load_matrix_sync(bh, khi + jt * 16 * 40 + ks * 16, 40);
                wmma::load_matrix_sync(bl, klo + jt * 16 * 40 + ks * 16, 40);
                wmma::mma_sync(c, ah[ks], bh, c);
                wmma::mma_sync(c, ah[ks], bl, c);
                wmma::mma_sync(c, al[ks], bh, c);
            }
            wmma::store_matrix_sync(Sb + it * 16 * 260 + jt * 16, c, 260, wmma::mem_row_major);
        }
    }
    __syncthreads();

    // ---- Phase C: softmax rows (warp w owns rows w*8 .. w*8+7) ----
    for (int rr = 0; rr < 8; rr++) {
        int r = w * 8 + rr;
        int i = qq * 64 + r;
        const float* pr = p2 + ((size_t)hh << 16) + (size_t)i * 256;
        float vals[8];
        float mx = -1e30f;
#pragma unroll
        for (int k = 0; k < 8; k++) {
            int j = k * 32 + lane;
            float v = Sb[r * 260 + j] + pr[j];
            vals[k] = v;
            mx = fmaxf(mx, v);
        }
#pragma unroll
        for (int o = 16; o > 0; o >>= 1) {
            mx = fmaxf(mx, __shfl_xor_sync(0xffffffffu, mx, o));
        }
        float sum = 0.f;
#pragma unroll
        for (int k = 0; k < 8; k++) {
            float p = __expf(vals[k] - mx);
            vals[k] = p;
            sum += p;
        }
#pragma unroll
        for (int o = 16; o > 0; o >>= 1) {
            sum += __shfl_xor_sync(0xffffffffu, sum, o);
        }
#pragma unroll
        for (int k = 0; k < 8; k++) {
            __nv_bfloat16 hi;
            __nv_bfloat16 lo;
            split1(vals[k], hi, lo);
            phi[r * 264 + k * 32 + lane] = hi;
            plo[r * 264 + k * 32 + lane] = lo;
        }
        if (lane == 0) {
            linv[r] = 1.f / sum;
        }
    }
    __syncthreads();

    // ---- Phase D: out = P~ @ V (3-term split), scale by 1/l, write hi/lo ----
    {
        int it = w >> 1;
        int dt = w & 1;
        wmma::fragment<wmma::accumulator, 16, 16, 16, float> c;
        wmma::fill_fragment(c, 0.0f);
#pragma unroll
        for (int ks = 0; ks < 16; ks++) {
            wmma::fragment<wmma::matrix_a, 16, 16, 16, __nv_bfloat16, wmma::row_major> ah;
            wmma::fragment<wmma::matrix_a, 16, 16, 16, __nv_bfloat16, wmma::row_major> al;
            wmma::fragment<wmma::matrix_b, 16, 16, 16, __nv_bfloat16, wmma::row_major> bh;
            wmma::fragment<wmma::matrix_b, 16, 16, 16, __nv_bfloat16, wmma::row_major> bl;
            wmma::load_matrix_sync(ah, phi + it * 16 * 264 + ks * 16, 264);
            wmma::load_matrix_sync(al, plo + it * 16 * 264 + ks * 16, 264);
            wmma::load_matrix_sync(bh, vhi + ks * 16 * 40 + dt * 16, 40);
            wmma::load_matrix_sync(bl, vlo + ks * 16 * 40 + dt * 16, 40);
            wmma::mma_sync(c, ah, bh, c);
            wmma::mma_sync(c, ah, bl, c);
            wmma::mma_sync(c, al, bh, c);
        }
        float* stg = Sb + w * 320;   // S region is dead now
        wmma::store_matrix_sync(stg, c, 20, wmma::mem_row_major);
        __syncwarp();
#pragma unroll
        for (int e = 0; e < 8; e++) {
            int idx = lane * 8 + e;
            int rr = idx >> 4;
            int cc = idx & 15;
            int r = it * 16 + rr;
            int i = qq * 64 + r;
            float val = stg[rr * 20 + cc] * linv[r];
            __nv_bfloat16 hi;
            __nv_bfloat16 lo;
            split1(val, hi, lo);
            size_t ofs = (((size_t)(b * NWIN + i)) * WSZ + m) * CDIM + 128 + hh * 32 + dt * 16 + cc;
            g_ahi[ofs] = hi;
            g_alo[ofs] = lo;
        }
    }
}

// ---------------------------------------------------------------------------
extern "C" void kernel_launch(void* const* d_in, const int* in_sizes, int n_in,
                              void* d_out, int out_size) {
    const float* x   = (const float*)d_in[0];
    const float* Wq  = (const float*)d_in[1];
    const float* Wkv = (const float*)d_in[2];
    const float* Wo  = (const float*)d_in[3];
    const float* bo  = (const float*)d_in[4];
    const float* p1  = (const float*)d_in[5];
    const float* p2  = (const float*)d_in[6];
    float* out = (float*)d_out;

    cudaFuncSetAttribute(attn2_tc, cudaFuncAttributeMaxDynamicSharedMemorySize, TC_SMEM);

    prep_kernel<<<768, 256>>>(p1, Wq, Wkv, Wo);
    split_x<<<2048, 256>>>(x);
    gemm_wmma<<<dim3(6, 512), 256>>>(0, (float*)0, (const float*)0);
    attn1_kernel<<<dim3(256, 4, 4), 64>>>();
    attn2_tc<<<dim3(256, 4, 4), 256, TC_SMEM>>>(p2);
    gemm_wmma<<<dim3(2, 512), 256>>>(1, out, bo);
}

// round 10
// speedup vs baseline: 1.1298x; 1.1298x over previous
#include <cuda_runtime.h>
#include <cuda_bf16.h>
#include <mma.h>
#include <math.h>

using namespace nvcuda;

#define NB    4
#define SS    128
#define CDIM  256
#define NHH   4
#define DHH   32
#define NWIN  256
#define WSZ   64
#define MTOT  (NB*SS*SS)
#define NQKV  768
#define QSCALE 0.17677669529663687f

typedef unsigned long long ull;

// ---------------- scratch ----------------
__device__ float g_q  [MTOT * CDIM];
__device__ float g_kv [MTOT * 2 * CDIM];
__device__ __nv_bfloat16 g_xhi[MTOT * CDIM];
__device__ __nv_bfloat16 g_xlo[MTOT * CDIM];
__device__ __nv_bfloat16 g_ahi[MTOT * CDIM];
__device__ __nv_bfloat16 g_alo[MTOT * CDIM];
__device__ __nv_bfloat16 g_whi[CDIM * NQKV];
__device__ __nv_bfloat16 g_wlo[CDIM * NQKV];
__device__ __nv_bfloat16 g_wohi[CDIM * CDIM];
__device__ __nv_bfloat16 g_wolo[CDIM * CDIM];
__device__ float g_pos1t[NHH * WSZ * WSZ];

// ---------------- helpers (no braces inside asm strings) ----------------
union F2U {
    float2 f;
    ull u;
};
__device__ __forceinline__ ull f2pack(float x, float y) {
    F2U t; t.f = make_float2(x, y); return t.u;
}
__device__ __forceinline__ float2 f2unpack(ull v) {
    F2U t; t.u = v; return t.f;
}
__device__ __forceinline__ ull ffma2(ull a, ull b, ull c) {
    ull d;
    asm("fma.rn.f32x2 %0,%1,%2,%3;" : "=l"(d) : "l"(a), "l"(b), "l"(c));
    return d;
}
__device__ __forceinline__ ull fmul2(ull a, ull b) {
    ull d;
    asm("mul.rn.f32x2 %0,%1,%2;" : "=l"(d) : "l"(a), "l"(b));
    return d;
}
__device__ __forceinline__ void split1(float x, __nv_bfloat16& h, __nv_bfloat16& l) {
    h = __float2bfloat16(x);
    l = __float2bfloat16(x - __bfloat162float(h));
}
__device__ __forceinline__ void cpasync16(void* s, const void* g) {
    unsigned saddr = (unsigned)__cvta_generic_to_shared(s);
    asm volatile("cp.async.cg.shared.global [%0], [%1], 16;" :: "r"(saddr), "l"(g));
}
__device__ __forceinline__ void cpcommit() {
    asm volatile("cp.async.commit_group;");
}
__device__ __forceinline__ void cpwait0() {
    asm volatile("cp.async.wait_group 0;");
}
__device__ __forceinline__ void cpwait1() {
    asm volatile("cp.async.wait_group 1;");
}

// ---------------- merged prep: pos1 transpose + weight splits ----------------
__global__ void prep_kernel(const float* __restrict__ p1,
                            const float* __restrict__ Wq,
                            const float* __restrict__ Wkv,
                            const float* __restrict__ Wo) {
    int idx = blockIdx.x * blockDim.x + threadIdx.x;
    int stride = gridDim.x * blockDim.x;
    for (int i = idx; i < NHH * WSZ * WSZ; i += stride) {
        int hh = i / (WSZ * WSZ);
        int rem = i - hh * WSZ * WSZ;
        int r = rem / WSZ;
        int c = rem % WSZ;
        g_pos1t[(hh * WSZ + c) * WSZ + r] = p1[i];
    }
    for (int i = idx; i < CDIM * CDIM; i += stride) {
        split1(Wo[i], g_wohi[i], g_wolo[i]);
    }
    for (int i = idx; i < CDIM * NQKV; i += stride) {
        int k = i / NQKV;
        int c = i % NQKV;
        float v = (c < 256) ? Wq[k * 256 + c] : Wkv[k * 512 + (c - 256)];
        split1(v, g_whi[i], g_wlo[i]);
    }
}

// ---------------- x split ----------------
__global__ void split_x(const float* __restrict__ src) {
    int idx = blockIdx.x * blockDim.x + threadIdx.x;
    int stride = gridDim.x * blockDim.x;
    const int n4 = MTOT * CDIM / 4;
    for (int i = idx; i < n4; i += stride) {
        float4 v = ((const float4*)src)[i];
        __nv_bfloat16 h4[4];
        __nv_bfloat16 l4[4];
        split1(v.x, h4[0], l4[0]);
        split1(v.y, h4[1], l4[1]);
        split1(v.z, h4[2], l4[2]);
        split1(v.w, h4[3], l4[3]);
        ((uint2*)g_xhi)[i] = *(uint2*)h4;
        ((uint2*)g_xlo)[i] = *(uint2*)l4;
    }
}

// ---------------- WMMA split-bf16 GEMM, cp.async double-buffered ------------
__device__ __forceinline__ int remap_row(int row) {
    int b = row >> 14;
    int n = (row >> 6) & 255;
    int m = row & 63;
    int h = ((n >> 4) << 3) + (m >> 3);
    int w = ((n & 15) << 3) + (m & 7);
    return (b << 14) + (h << 7) + w;
}

__global__ __launch_bounds__(256) void gemm_wmma(
    int mode, float* __restrict__ outp, const float* __restrict__ bo)
{
    const int Ntot = mode ? 256 : NQKV;
    const __nv_bfloat16* __restrict__ Ahi = mode ? g_ahi : g_xhi;
    const __nv_bfloat16* __restrict__ Alo = mode ? g_alo : g_xlo;
    const __nv_bfloat16* __restrict__ Bhi = mode ? g_wohi : g_whi;
    const __nv_bfloat16* __restrict__ Blo = mode ? g_wolo : g_wlo;

    __shared__ __align__(32) __nv_bfloat16 As[2][2][128][24];
    __shared__ __align__(32) __nv_bfloat16 Bs[2][2][16][136];

    const int tid = threadIdx.x;
    const int wid = tid >> 5;
    const int lane = tid & 31;
    const int nb0 = blockIdx.x * 128;
    const int mrow0 = blockIdx.y * 128;
    const int m0w = (wid & 3) * 32;
    const int n0w = (wid >> 2) * 64;

    wmma::fragment<wmma::accumulator, 16, 16, 16, float> cfrag[2][4];
#pragma unroll
    for (int mi = 0; mi < 2; mi++) {
#pragma unroll
        for (int ni = 0; ni < 4; ni++) {
            wmma::fill_fragment(cfrag[mi][ni], 0.0f);
        }
    }

    const int arow = tid >> 1;
    const int acol8 = (tid & 1) * 8;
    const int bkr = tid >> 4;
    const int bnc8 = (tid & 15) * 8;

    {
        cpasync16(&As[0][0][arow][acol8],
                  Ahi + (size_t)(mrow0 + arow) * 256 + acol8);
        cpasync16(&As[0][1][arow][acol8],
                  Alo + (size_t)(mrow0 + arow) * 256 + acol8);
        cpasync16(&Bs[0][0][bkr][bnc8],
                  Bhi + (size_t)(bkr) * Ntot + nb0 + bnc8);
        cpasync16(&Bs[0][1][bkr][bnc8],
                  Blo + (size_t)(bkr) * Ntot + nb0 + bnc8);
        cpcommit();
    }

    const int NT = 256 / 16;
    for (int t = 0; t < NT; t++) {
        int buf = t & 1;
        if (t + 1 < NT) {
            int kn = (t + 1) * 16;
            cpasync16(&As[1 - buf][0][arow][acol8],
                      Ahi + (size_t)(mrow0 + arow) * 256 + kn + acol8);
            cpasync16(&As[1 - buf][1][arow][acol8],
                      Alo + (size_t)(mrow0 + arow) * 256 + kn + acol8);
            cpasync16(&Bs[1 - buf][0][bkr][bnc8],
                      Bhi + (size_t)(kn + bkr) * Ntot + nb0 + bnc8);
            cpasync16(&Bs[1 - buf][1][bkr][bnc8],
                      Blo + (size_t)(kn + bkr) * Ntot + nb0 + bnc8);
            cpcommit();
            cpwait1();
        } else {
            cpwait0();
        }
        __syncthreads();

        wmma::fragment<wmma::matrix_a, 16, 16, 16, __nv_bfloat16, wmma::row_major> afh[2];
        wmma::fragment<wmma::matrix_a, 16, 16, 16, __nv_bfloat16, wmma::row_major> afl[2];
        wmma::load_matrix_sync(afh[0], &As[buf][0][m0w][0], 24);
        wmma::load_matrix_sync(afh[1], &As[buf][0][m0w + 16][0], 24);
        wmma::load_matrix_sync(afl[0], &As[buf][1][m0w][0], 24);
        wmma::load_matrix_sync(afl[1], &As[buf][1][m0w + 16][0], 24);
#pragma unroll
        for (int ni = 0; ni < 4; ni++) {
            wmma::fragment<wmma::matrix_b, 16, 16, 16, __nv_bfloat16, wmma::row_major> bfh;
            wmma::fragment<wmma::matrix_b, 16, 16, 16, __nv_bfloat16, wmma::row_major> bfl;
            wmma::load_matrix_sync(bfh, &Bs[buf][0][0][n0w + ni * 16], 136);
            wmma::load_matrix_sync(bfl, &Bs[buf][1][0][n0w + ni * 16], 136);
#pragma unroll
            for (int mi = 0; mi < 2; mi++) {
                wmma::mma_sync(cfrag[mi][ni], afh[mi], bfh, cfrag[mi][ni]);
                wmma::mma_sync(cfrag[mi][ni], afh[mi], bfl, cfrag[mi][ni]);
                wmma::mma_sync(cfrag[mi][ni], afl[mi], bfh, cfrag[mi][ni]);
            }
        }
        __syncthreads();
    }

    if (mode == 0) {
#pragma unroll
        for (int mi = 0; mi < 2; mi++) {
#pragma unroll
            for (int ni = 0; ni < 4; ni++) {
                int row = mrow0 + m0w + mi * 16;
                int col = nb0 + n0w + ni * 16;
                if (col < 256) {
#pragma unroll
                    for (int e = 0; e < cfrag[mi][ni].num_elements; e++) {
                        cfrag[mi][ni].x[e] *= QSCALE;
                    }
                    wmma::store_matrix_sync(g_q + (size_t)row * 256 + col,
                                            cfrag[mi][ni], 256, wmma::mem_row_major);
                } else {
                    wmma::store_matrix_sync(g_kv + (size_t)row * 512 + (col - 256),
                                            cfrag[mi][ni], 512, wmma::mem_row_major);
                }
            }
        }
    } else {
        float* stg = (float*)&As[0][0][0][0];
        float* mystg = stg + wid * 256;
#pragma unroll
        for (int mi = 0; mi < 2; mi++) {
#pragma unroll
            for (int ni = 0; ni < 4; ni++) {
                wmma::store_matrix_sync(mystg, cfrag[mi][ni], 16, wmma::mem_row_major);
                __syncwarp();
                int row0 = mrow0 + m0w + mi * 16;
                int col0 = nb0 + n0w + ni * 16;
#pragma unroll
                for (int e = 0; e < 8; e++) {
                    int idx = lane * 8 + e;
                    int r = idx >> 4;
                    int c = idx & 15;
                    int grow = remap_row(row0 + r);
                    outp[(size_t)grow * 256 + col0 + c] = mystg[r * 16 + c] + bo[col0 + c];
                }
                __syncwarp();
            }
        }
    }
}

// ---------------- attention branch 1 (within-window, seq=64) ----------------
__global__ __launch_bounds__(64) void attn1_kernel() {
    int n  = blockIdx.x;
    int hh = blockIdx.y;
    int b  = blockIdx.z;
    int i  = threadIdx.x;

    __shared__ float ks[WSZ][36];
    __shared__ float vs[WSZ][36];

    int h = ((n >> 4) << 3) + (i >> 3);
    int w = ((n & 15) << 3) + (i & 7);
    size_t grow = ((size_t)b << 14) + (h << 7) + w;

    {
        const float4* kp = (const float4*)(g_kv + grow * 512 + hh * DHH);
        const float4* vp = (const float4*)(g_kv + grow * 512 + 256 + hh * DHH);
#pragma unroll
        for (int d4 = 0; d4 < 8; d4++) {
            *(float4*)(&ks[i][d4 * 4]) = kp[d4];
            *(float4*)(&vs[i][d4 * 4]) = vp[d4];
        }
    }
    ull qr2[16];
    {
        const ulonglong2* qp = (const ulonglong2*)(g_q + grow * 256 + hh * DHH);
#pragma unroll
        for (int d4 = 0; d4 < 8; d4++) {
            ulonglong2 q4 = qp[d4];
            qr2[2 * d4]     = q4.x;
            qr2[2 * d4 + 1] = q4.y;
        }
    }
    __syncthreads();

    const float* pos = g_pos1t + hh * WSZ * WSZ;
    float mrun = -INFINITY;
    float l = 0.f;
    ull acc2[16];
#pragma unroll
    for (int t = 0; t < 16; t++) acc2[t] = 0ULL;

#pragma unroll 2
    for (int j = 0; j < WSZ; j++) {
        float pb = pos[j * WSZ + i];
        const ulonglong2* kp2 = (const ulonglong2*)(&ks[j][0]);
        ull sA = 0ULL;
        ull sB = 0ULL;
        ull sC = 0ULL;
        ull sD = 0ULL;
#pragma unroll
        for (int t = 0; t < 4; t++) {
            ulonglong2 k0 = kp2[t];
            ulonglong2 k1 = kp2[t + 4];
            sA = ffma2(qr2[2 * t],     k0.x, sA);
            sB = ffma2(qr2[2 * t + 1], k0.y, sB);
            sC = ffma2(qr2[2 * t + 8], k1.x, sC);
            sD = ffma2(qr2[2 * t + 9], k1.y, sD);
        }
        float2 a = f2unpack(sA);
        float2 bb = f2unpack(sB);
        float2 cc = f2unpack(sC);
        float2 dd = f2unpack(sD);
        float s = ((a.x + a.y) + (bb.x + bb.y)) + ((cc.x + cc.y) + (dd.x + dd.y)) + pb;
        if (s > mrun) {
            float c = __expf(mrun - s);
            mrun = s;
            l *= c;
            ull cc2 = f2pack(c, c);
#pragma unroll
            for (int t = 0; t < 16; t++) acc2[t] = fmul2(acc2[t], cc2);
        }
        float p = __expf(s - mrun);
        l += p;
        ull pp2 = f2pack(p, p);
        const ulonglong2* vp2 = (const ulonglong2*)(&vs[j][0]);
#pragma unroll
        for (int t = 0; t < 8; t++) {
            ulonglong2 vv = vp2[t];
            acc2[2 * t]     = ffma2(pp2, vv.x, acc2[2 * t]);
            acc2[2 * t + 1] = ffma2(pp2, vv.y, acc2[2 * t + 1]);
        }
    }
    float inv = 1.f / l;
    size_t obase = (((size_t)(b * NWIN + n) * WSZ) + i) * CDIM + hh * DHH;
#pragma unroll
    for (int t = 0; t < 8; t++) {
        float2 p0 = f2unpack(acc2[2 * t]);
        float2 p1 = f2unpack(acc2[2 * t + 1]);
        __nv_bfloat16 h4[4];
        __nv_bfloat16 l4[4];
        split1(p0.x * inv, h4[0], l4[0]);
        split1(p0.y * inv, h4[1], l4[1]);
        split1(p1.x * inv, h4[2], l4[2]);
        split1(p1.y * inv, h4[3], l4[3]);
        *(uint2*)(g_ahi + obase + t * 4) = *(uint2*)h4;
        *(uint2*)(g_alo + obase + t * 4) = *(uint2*)l4;
    }
}

// ---------------- attention branch 2 : WMMA tensor-core v2 ------------------
// 32 queries x 256 keys per CTA; 103 KB smem -> 2 CTAs/SM.
// Smem byte offsets:
#define T2_QHI  0
#define T2_QLO  2048
#define T2_KHI  4096
#define T2_KLO  20480
#define T2_VHI  36864
#define T2_VLO  53248
#define T2_SP   69632
#define T2_LNV  102912
#define T2_SMEM 103040

__global__ __launch_bounds__(256, 2) void attn2_tc(const float* __restrict__ p2) {
    const int m  = blockIdx.x >> 3;
    const int qo = blockIdx.x & 7;       // query block: rows qo*32 .. +31
    const int hh = blockIdx.y;
    const int b  = blockIdx.z;
    const int tid = threadIdx.x;
    const int w = tid >> 5;
    const int lane = tid & 31;

    extern __shared__ char smc[];
    __nv_bfloat16* qhi = (__nv_bfloat16*)(smc + T2_QHI);
    __nv_bfloat16* qlo = (__nv_bfloat16*)(smc + T2_QLO);
    __nv_bfloat16* khi = (__nv_bfloat16*)(smc + T2_KHI);
    __nv_bfloat16* klo = (__nv_bfloat16*)(smc + T2_KLO);
    __nv_bfloat16* vhi = (__nv_bfloat16*)(smc + T2_VHI);
    __nv_bfloat16* vlo = (__nv_bfloat16*)(smc + T2_VLO);
    float* Sb   = (float*)(smc + T2_SP);   // 32 rows x 260 fp32 (reused for P)
    float* linv = (float*)(smc + T2_LNV);

    // ---- Phase A: load fp32 q/k/v, split into bf16 hi/lo smem ----
    for (int idx = tid; idx < 32 * 32; idx += 256) {
        int r = idx >> 5;
        int d = idx & 31;
        int i = qo * 32 + r;
        int h = ((i >> 4) << 3) + (m >> 3);
        int ww = ((i & 15) << 3) + (m & 7);
        size_t grow = ((size_t)b << 14) + (h << 7) + ww;
        float v = g_q[grow * 256 + 128 + hh * 32 + d];
        __nv_bfloat16 hi;
        __nv_bfloat16 lo;
        split1(v, hi, lo);
        qhi[r * 32 + d] = hi;
        qlo[r * 32 + d] = lo;
    }
    for (int idx = tid; idx < 256 * 32; idx += 256) {
        int r = idx >> 5;
        int d = idx & 31;
        int h = ((r >> 4) << 3) + (m >> 3);
        int ww = ((r & 15) << 3) + (m & 7);
        size_t gk = ((size_t)b << 14) + (h << 7) + ww;
        float kv = g_kv[gk * 512 + 128 + hh * 32 + d];
        float vv = g_kv[gk * 512 + 384 + hh * 32 + d];
        __nv_bfloat16 hi;
        __nv_bfloat16 lo;
        split1(kv, hi, lo);
        khi[idx] = hi;
        klo[idx] = lo;
        split1(vv, hi, lo);
        vhi[idx] = hi;
        vlo[idx] = lo;
    }
    __syncthreads();

    // ---- Phase B: S = Q @ K^T, warp w owns col-tiles jt = 2w, 2w+1 ----
    {
        wmma::fragment<wmma::matrix_a, 16, 16, 16, __nv_bfloat16, wmma::row_major> ah[2][2];
        wmma::fragment<wmma::matrix_a, 16, 16, 16, __nv_bfloat16, wmma::row_major> al[2][2];
#pragma unroll
        for (int it = 0; it < 2; it++) {
#pragma unroll
            for (int ks = 0; ks < 2; ks++) {
                wmma::load_matrix_sync(ah[it][ks], qhi + it * 16 * 32 + ks * 16, 32);
                wmma::load_matrix_sync(al[it][ks], qlo + it * 16 * 32 + ks * 16, 32);
            }
        }
#pragma unroll
        for (int jj = 0; jj < 2; jj++) {
            int jt = w * 2 + jj;
            wmma::fragment<wmma::matrix_b, 16, 16, 16, __nv_bfloat16, wmma::col_major> bh[2];
            wmma::fragment<wmma::matrix_b, 16, 16, 16, __nv_bfloat16, wmma::col_major> bl[2];
#pragma unroll
            for (int ks = 0; ks < 2; ks++) {
                wmma::load_matrix_sync(bh[ks], khi + jt * 16 * 32 + ks * 16, 32);
                wmma::load_matrix_sync(bl[ks], klo + jt * 16 * 32 + ks * 16, 32);
            }
#pragma unroll
            for (int it = 0; it < 2; it++) {
                wmma::fragment<wmma::accumulator, 16, 16, 16, float> c;
                wmma::fill_fragment(c, 0.0f);
#pragma unroll
                for (int ks = 0; ks < 2; ks++) {
                    wmma::mma_sync(c, ah[it][ks], bh[ks], c);
                    wmma::mma_sync(c, ah[it][ks], bl[ks], c);
                    wmma::mma_sync(c, al[it][ks], bh[ks], c);
                }
                wmma::store_matrix_sync(Sb + it * 16 * 260 + jt * 16, c, 260, wmma::mem_row_major);
            }
        }
    }
    __syncthreads();

    // ---- Phase C: softmax, warp w owns rows 4w..4w+3; write P into S buffer ----
    for (int rr = 0; rr < 4; rr++) {
        int r = w * 4 + rr;
        int i = qo * 32 + r;
        const float* pr = p2 + ((size_t)hh << 16) + (size_t)i * 256;
        float vals[8];
        float mx = -1e30f;
#pragma unroll
        for (int k = 0; k < 8; k++) {
            int j = k * 32 + lane;
            float v = Sb[r * 260 + j] + pr[j];
            vals[k] = v;
            mx = fmaxf(mx, v);
        }
#pragma unroll
        for (int o = 16; o > 0; o >>= 1) {
            mx = fmaxf(mx, __shfl_xor_sync(0xffffffffu, mx, o));
        }
        float sum = 0.f;
#pragma unroll
        for (int k = 0; k < 8; k++) {
            float p = __expf(vals[k] - mx);
            vals[k] = p;
            sum += p;
        }
#pragma unroll
        for (int o = 16; o > 0; o >>= 1) {
            sum += __shfl_xor_sync(0xffffffffu, sum, o);
        }
        // all reads of this row are done (shfl.sync converged) -> overwrite with P
        __nv_bfloat16* prow = (__nv_bfloat16*)(Sb + r * 260);   // 520 bf16 slots
#pragma unroll
        for (int k = 0; k < 8; k++) {
            __nv_bfloat16 hi;
            __nv_bfloat16 lo;
            split1(vals[k], hi, lo);
            prow[k * 32 + lane] = hi;           // hi at elems 0..255
            prow[264 + k * 32 + lane] = lo;     // lo at elems 264..519
        }
        if (lane == 0) {
            linv[r] = 1.f / sum;
        }
    }
    __syncthreads();

    // ---- Phase D: out = P @ V, split-k across warp pairs ----
    {
        int tile = w >> 1;          // 0..3 : (it, dt) = (tile>>1, tile&1)
        int it = tile >> 1;
        int dt = tile & 1;
        int kh = w & 1;             // k half: keys kh*128 .. +127
        const __nv_bfloat16* pbase = (const __nv_bfloat16*)Sb;
        wmma::fragment<wmma::accumulator, 16, 16, 16, float> c;
        wmma::fill_fragment(c, 0.0f);
#pragma unroll
        for (int kk = 0; kk < 8; kk++) {
            int ks = kh * 8 + kk;
            wmma::fragment<wmma::matrix_a, 16, 16, 16, __nv_bfloat16, wmma::row_major> ah;
            wmma::fragment<wmma::matrix_a, 16, 16, 16, __nv_bfloat16, wmma::row_major> al;
            wmma::fragment<wmma::matrix_b, 16, 16, 16, __nv_bfloat16, wmma::row_major> bh;
            wmma::fragment<wmma::matrix_b, 16, 16, 16, __nv_bfloat16, wmma::row_major> bl;
            wmma::load_matrix_sync(ah, pbase + it * 16 * 520 + ks * 16, 520);
            wmma::load_matrix_sync(al, pbase + it * 16 * 520 + 264 + ks * 16, 520);
            wmma::load_matrix_sync(bh, vhi + ks * 16 * 32 + dt * 16, 32);
            wmma::load_matrix_sync(bl, vlo + ks * 16 * 32 + dt * 16, 32);
            wmma::mma_sync(c, ah, bh, c);
            wmma::mma_sync(c, ah, bl, c);
            wmma::mma_sync(c, al, bh, c);
        }
        // stage into dead K region: warp w gets 16x20 fp32
        float* stg = (float*)khi + w * 320;
        wmma::store_matrix_sync(stg, c, 20, wmma::mem_row_major);
    }
    __syncthreads();

    // ---- writeout: warps 0..3 combine the two k-halves of tile w ----
    if (w < 4) {
        int it = w >> 1;
        int dt = w & 1;
        const float* s0 = (const float*)khi + (2 * w) * 320;
        const float* s1 = (const float*)khi + (2 * w + 1) * 320;
        // thread covers 8 consecutive cols in one row half
        int idx0 = lane * 8;
        int rr = idx0 >> 4;
        int cb = idx0 & 15;        // 0 or 8
        int r = it * 16 + rr;
        int i = qo * 32 + r;
        float li = linv[r];
        __nv_bfloat16 h8[8];
        __nv_bfloat16 l8[8];
#pragma unroll
        for (int e = 0; e < 8; e++) {
            float val = (s0[rr * 20 + cb + e] + s1[rr * 20 + cb + e]) * li;
            split1(val, h8[e], l8[e]);
        }
        size_t ofs = (((size_t)(b * NWIN + i)) * WSZ + m) * CDIM + 128 + hh * 32 + dt * 16 + cb;
        *(uint4*)(g_ahi + ofs) = *(uint4*)h8;
        *(uint4*)(g_alo + ofs) = *(uint4*)l8;
    }
}

// ---------------------------------------------------------------------------
extern "C" void kernel_launch(void* const* d_in, const int* in_sizes, int n_in,
                              void* d_out, int out_size) {
    const float* x   = (const float*)d_in[0];
    const float* Wq  = (const float*)d_in[1];
    const float* Wkv = (const float*)d_in[2];
    const float* Wo  = (const float*)d_in[3];
    const float* bo  = (const float*)d_in[4];
    const float* p1  = (const float*)d_in[5];
    const float* p2  = (const float*)d_in[6];
    float* out = (float*)d_out;

    cudaFuncSetAttribute(attn2_tc, cudaFuncAttributeMaxDynamicSharedMemorySize, T2_SMEM);

    prep_kernel<<<768, 256>>>(p1, Wq, Wkv, Wo);
    split_x<<<2048, 256>>>(x);
    gemm_wmma<<<dim3(6, 512), 256>>>(0, (float*)0, (const float*)0);
    attn1_kernel<<<dim3(256, 4, 4), 64>>>();
    attn2_tc<<<dim3(512, 4, 4), 256, T2_SMEM>>>(p2);
    gemm_wmma<<<dim3(2, 512), 256>>>(1, out, bo);
}

// round 11
// speedup vs baseline: 1.2364x; 1.0943x over previous
#include <cuda_runtime.h>
#include <cuda_bf16.h>
#include <mma.h>
#include <math.h>

using namespace nvcuda;

#define NB    4
#define SS    128
#define CDIM  256
#define NHH   4
#define DHH   32
#define NWIN  256
#define WSZ   64
#define MTOT  (NB*SS*SS)
#define NQKV  768
#define QSCALE 0.17677669529663687f

typedef unsigned long long ull;

// ---------------- scratch ----------------
__device__ float g_q  [MTOT * CDIM];
__device__ float g_kv [MTOT * 2 * CDIM];
__device__ __nv_bfloat16 g_xhi[MTOT * CDIM];
__device__ __nv_bfloat16 g_xlo[MTOT * CDIM];
__device__ __nv_bfloat16 g_ahi[MTOT * CDIM];
__device__ __nv_bfloat16 g_alo[MTOT * CDIM];
__device__ __nv_bfloat16 g_whi[CDIM * NQKV];
__device__ __nv_bfloat16 g_wlo[CDIM * NQKV];
__device__ __nv_bfloat16 g_wohi[CDIM * CDIM];
__device__ __nv_bfloat16 g_wolo[CDIM * CDIM];
__device__ float g_pos1t[NHH * WSZ * WSZ];
__device__ float g_pos2t[NHH * NWIN * NWIN];

// ---------------- helpers (no braces inside asm strings) ----------------
union F2U {
    float2 f;
    ull u;
};
__device__ __forceinline__ ull f2pack(float x, float y) {
    F2U t; t.f = make_float2(x, y); return t.u;
}
__device__ __forceinline__ float2 f2unpack(ull v) {
    F2U t; t.u = v; return t.f;
}
__device__ __forceinline__ ull ffma2(ull a, ull b, ull c) {
    ull d;
    asm("fma.rn.f32x2 %0,%1,%2,%3;" : "=l"(d) : "l"(a), "l"(b), "l"(c));
    return d;
}
__device__ __forceinline__ ull fmul2(ull a, ull b) {
    ull d;
    asm("mul.rn.f32x2 %0,%1,%2;" : "=l"(d) : "l"(a), "l"(b));
    return d;
}
__device__ __forceinline__ void split1(float x, __nv_bfloat16& h, __nv_bfloat16& l) {
    h = __float2bfloat16(x);
    l = __float2bfloat16(x - __bfloat162float(h));
}
__device__ __forceinline__ void cpasync16(void* s, const void* g) {
    unsigned saddr = (unsigned)__cvta_generic_to_shared(s);
    asm volatile("cp.async.cg.shared.global [%0], [%1], 16;" :: "r"(saddr), "l"(g));
}
__device__ __forceinline__ void cpcommit() {
    asm volatile("cp.async.commit_group;");
}
__device__ __forceinline__ void cpwait0() {
    asm volatile("cp.async.wait_group 0;");
}
__device__ __forceinline__ void cpwait1() {
    asm volatile("cp.async.wait_group 1;");
}

// ---------------- merged prep: pos transposes + weight splits ----------------
__global__ void prep_kernel(const float* __restrict__ p1,
                            const float* __restrict__ p2,
                            const float* __restrict__ Wq,
                            const float* __restrict__ Wkv,
                            const float* __restrict__ Wo) {
    int idx = blockIdx.x * blockDim.x + threadIdx.x;
    int stride = gridDim.x * blockDim.x;
    for (int i = idx; i < NHH * WSZ * WSZ; i += stride) {
        int hh = i / (WSZ * WSZ);
        int rem = i - hh * WSZ * WSZ;
        int r = rem / WSZ;
        int c = rem % WSZ;
        g_pos1t[(hh * WSZ + c) * WSZ + r] = p1[i];
    }
    for (int i = idx; i < NHH * NWIN * NWIN; i += stride) {
        int hh = i / (NWIN * NWIN);
        int rem = i - hh * NWIN * NWIN;
        int r = rem / NWIN;
        int c = rem % NWIN;
        g_pos2t[(hh * NWIN + c) * NWIN + r] = p2[i];
    }
    for (int i = idx; i < CDIM * CDIM; i += stride) {
        split1(Wo[i], g_wohi[i], g_wolo[i]);
    }
    for (int i = idx; i < CDIM * NQKV; i += stride) {
        int k = i / NQKV;
        int c = i % NQKV;
        float v = (c < 256) ? Wq[k * 256 + c] : Wkv[k * 512 + (c - 256)];
        split1(v, g_whi[i], g_wlo[i]);
    }
}

// ---------------- x split ----------------
__global__ void split_x(const float* __restrict__ src) {
    int idx = blockIdx.x * blockDim.x + threadIdx.x;
    int stride = gridDim.x * blockDim.x;
    const int n4 = MTOT * CDIM / 4;
    for (int i = idx; i < n4; i += stride) {
        float4 v = ((const float4*)src)[i];
        __nv_bfloat16 h4[4];
        __nv_bfloat16 l4[4];
        split1(v.x, h4[0], l4[0]);
        split1(v.y, h4[1], l4[1]);
        split1(v.z, h4[2], l4[2]);
        split1(v.w, h4[3], l4[3]);
        ((uint2*)g_xhi)[i] = *(uint2*)h4;
        ((uint2*)g_xlo)[i] = *(uint2*)l4;
    }
}

// ---------------- WMMA split-bf16 GEMM, cp.async double-buffered ------------
__device__ __forceinline__ int remap_row(int row) {
    int b = row >> 14;
    int n = (row >> 6) & 255;
    int m = row & 63;
    int h = ((n >> 4) << 3) + (m >> 3);
    int w = ((n & 15) << 3) + (m & 7);
    return (b << 14) + (h << 7) + w;
}

__global__ __launch_bounds__(256) void gemm_wmma(
    int mode, float* __restrict__ outp, const float* __restrict__ bo)
{
    const int Ntot = mode ? 256 : NQKV;
    const __nv_bfloat16* __restrict__ Ahi = mode ? g_ahi : g_xhi;
    const __nv_bfloat16* __restrict__ Alo = mode ? g_alo : g_xlo;
    const __nv_bfloat16* __restrict__ Bhi = mode ? g_wohi : g_whi;
    const __nv_bfloat16* __restrict__ Blo = mode ? g_wolo : g_wlo;

    __shared__ __align__(32) __nv_bfloat16 As[2][2][128][24];
    __shared__ __align__(32) __nv_bfloat16 Bs[2][2][16][136];

    const int tid = threadIdx.x;
    const int wid = tid >> 5;
    const int lane = tid & 31;
    const int nb0 = blockIdx.x * 128;
    const int mrow0 = blockIdx.y * 128;
    const int m0w = (wid & 3) * 32;
    const int n0w = (wid >> 2) * 64;

    wmma::fragment<wmma::accumulator, 16, 16, 16, float> cfrag[2][4];
#pragma unroll
    for (int mi = 0; mi < 2; mi++) {
#pragma unroll
        for (int ni = 0; ni < 4; ni++) {
            wmma::fill_fragment(cfrag[mi][ni], 0.0f);
        }
    }

    const int arow = tid >> 1;
    const int acol8 = (tid & 1) * 8;
    const int bkr = tid >> 4;
    const int bnc8 = (tid & 15) * 8;

    {
        cpasync16(&As[0][0][arow][acol8],
                  Ahi + (size_t)(mrow0 + arow) * 256 + acol8);
        cpasync16(&As[0][1][arow][acol8],
                  Alo + (size_t)(mrow0 + arow) * 256 + acol8);
        cpasync16(&Bs[0][0][bkr][bnc8],
                  Bhi + (size_t)(bkr) * Ntot + nb0 + bnc8);
        cpasync16(&Bs[0][1][bkr][bnc8],
                  Blo + (size_t)(bkr) * Ntot + nb0 + bnc8);
        cpcommit();
    }

    const int NT = 256 / 16;
    for (int t = 0; t < NT; t++) {
        int buf = t & 1;
        if (t + 1 < NT) {
            int kn = (t + 1) * 16;
            cpasync16(&As[1 - buf][0][arow][acol8],
                      Ahi + (size_t)(mrow0 + arow) * 256 + kn + acol8);
            cpasync16(&As[1 - buf][1][arow][acol8],
                      Alo + (size_t)(mrow0 + arow) * 256 + kn + acol8);
            cpasync16(&Bs[1 - buf][0][bkr][bnc8],
                      Bhi + (size_t)(kn + bkr) * Ntot + nb0 + bnc8);
            cpasync16(&Bs[1 - buf][1][bkr][bnc8],
                      Blo + (size_t)(kn + bkr) * Ntot + nb0 + bnc8);
            cpcommit();
            cpwait1();
        } else {
            cpwait0();
        }
        __syncthreads();

        wmma::fragment<wmma::matrix_a, 16, 16, 16, __nv_bfloat16, wmma::row_major> afh[2];
        wmma::fragment<wmma::matrix_a, 16, 16, 16, __nv_bfloat16, wmma::row_major> afl[2];
        wmma::load_matrix_sync(afh[0], &As[buf][0][m0w][0], 24);
        wmma::load_matrix_sync(afh[1], &As[buf][0][m0w + 16][0], 24);
        wmma::load_matrix_sync(afl[0], &As[buf][1][m0w][0], 24);
        wmma::load_matrix_sync(afl[1], &As[buf][1][m0w + 16][0], 24);
#pragma unroll
        for (int ni = 0; ni < 4; ni++) {
            wmma::fragment<wmma::matrix_b, 16, 16, 16, __nv_bfloat16, wmma::row_major> bfh;
            wmma::fragment<wmma::matrix_b, 16, 16, 16, __nv_bfloat16, wmma::row_major> bfl;
            wmma::load_matrix_sync(bfh, &Bs[buf][0][0][n0w + ni * 16], 136);
            wmma::load_matrix_sync(bfl, &Bs[buf][1][0][n0w + ni * 16], 136);
#pragma unroll
            for (int mi = 0; mi < 2; mi++) {
                wmma::mma_sync(cfrag[mi][ni], afh[mi], bfh, cfrag[mi][ni]);
                wmma::mma_sync(cfrag[mi][ni], afh[mi], bfl, cfrag[mi][ni]);
                wmma::mma_sync(cfrag[mi][ni], afl[mi], bfh, cfrag[mi][ni]);
            }
        }
        __syncthreads();
    }

    if (mode == 0) {
#pragma unroll
        for (int mi = 0; mi < 2; mi++) {
#pragma unroll
            for (int ni = 0; ni < 4; ni++) {
                int row = mrow0 + m0w + mi * 16;
                int col = nb0 + n0w + ni * 16;
                if (col < 256) {
#pragma unroll
                    for (int e = 0; e < cfrag[mi][ni].num_elements; e++) {
                        cfrag[mi][ni].x[e] *= QSCALE;
                    }
                    wmma::store_matrix_sync(g_q + (size_t)row * 256 + col,
                                            cfrag[mi][ni], 256, wmma::mem_row_major);
                } else {
                    wmma::store_matrix_sync(g_kv + (size_t)row * 512 + (col - 256),
                                            cfrag[mi][ni], 512, wmma::mem_row_major);
                }
            }
        }
    } else {
        float* stg = (float*)&As[0][0][0][0];
        float* mystg = stg + wid * 256;
#pragma unroll
        for (int mi = 0; mi < 2; mi++) {
#pragma unroll
            for (int ni = 0; ni < 4; ni++) {
                wmma::store_matrix_sync(mystg, cfrag[mi][ni], 16, wmma::mem_row_major);
                __syncwarp();
                int row0 = mrow0 + m0w + mi * 16;
                int col0 = nb0 + n0w + ni * 16;
#pragma unroll
                for (int e = 0; e < 8; e++) {
                    int idx = lane * 8 + e;
                    int r = idx >> 4;
                    int c = idx & 15;
                    int grow = remap_row(row0 + r);
                    outp[(size_t)grow * 256 + col0 + c] = mystg[r * 16 + c] + bo[col0 + c];
                }
                __syncwarp();
            }
        }
    }
}

// ---------------- fused attention: attn2 blocks first, then attn1 groups ----
// grid (128, 4, 4), 256 threads, 73728 B dynamic smem.
//   blockIdx.x <  64 : attn2, m = blockIdx.x       (256 queries x 256 keys)
//   blockIdx.x >= 64 : attn1 group g = blockIdx.x-64, windows 4g..4g+3
#define AT_SMEM 73728

__global__ __launch_bounds__(256, 2) void attn_fused() {
    extern __shared__ float sm[];
    const int hh = blockIdx.y;
    const int b  = blockIdx.z;
    const int tid = threadIdx.x;

    if (blockIdx.x >= 64) {
        // ---------------- attn1: 4 windows per block ----------------
        const int g = blockIdx.x - 64;
        const int wloc = tid >> 6;        // window slot 0..3
        const int i = tid & 63;           // query position in window
        const int n = g * 4 + wloc;

        float* ks = sm;                   // [4][64][36]
        float* vs = sm + 4 * 64 * 36;

        int h = ((n >> 4) << 3) + (i >> 3);
        int w = ((n & 15) << 3) + (i & 7);
        size_t grow = ((size_t)b << 14) + (h << 7) + w;

        {
            const float4* kp = (const float4*)(g_kv + grow * 512 + hh * DHH);
            const float4* vp = (const float4*)(g_kv + grow * 512 + 256 + hh * DHH);
            float* kd = ks + (wloc * 64 + i) * 36;
            float* vd = vs + (wloc * 64 + i) * 36;
#pragma unroll
            for (int d4 = 0; d4 < 8; d4++) {
                *(float4*)(kd + d4 * 4) = kp[d4];
                *(float4*)(vd + d4 * 4) = vp[d4];
            }
        }
        ull qr2[16];
        {
            const ulonglong2* qp = (const ulonglong2*)(g_q + grow * 256 + hh * DHH);
#pragma unroll
            for (int d4 = 0; d4 < 8; d4++) {
                ulonglong2 q4 = qp[d4];
                qr2[2 * d4]     = q4.x;
                qr2[2 * d4 + 1] = q4.y;
            }
        }
        __syncthreads();

        const float* pos = g_pos1t + hh * WSZ * WSZ;
        float mrun = -INFINITY;
        float l = 0.f;
        ull acc2[16];
#pragma unroll
        for (int t = 0; t < 16; t++) acc2[t] = 0ULL;

        const float* kbase = ks + wloc * 64 * 36;
        const float* vbase = vs + wloc * 64 * 36;

#pragma unroll 2
        for (int j = 0; j < WSZ; j++) {
            float pb = pos[j * WSZ + i];
            const ulonglong2* kp2 = (const ulonglong2*)(kbase + j * 36);
            ull sA = 0ULL;
            ull sB = 0ULL;
            ull sC = 0ULL;
            ull sD = 0ULL;
#pragma unroll
            for (int t = 0; t < 4; t++) {
                ulonglong2 k0 = kp2[t];
                ulonglong2 k1 = kp2[t + 4];
                sA = ffma2(qr2[2 * t],     k0.x, sA);
                sB = ffma2(qr2[2 * t + 1], k0.y, sB);
                sC = ffma2(qr2[2 * t + 8], k1.x, sC);
                sD = ffma2(qr2[2 * t + 9], k1.y, sD);
            }
            float2 a = f2unpack(sA);
            float2 bb = f2unpack(sB);
            float2 cc = f2unpack(sC);
            float2 dd = f2unpack(sD);
            float s = ((a.x + a.y) + (bb.x + bb.y)) + ((cc.x + cc.y) + (dd.x + dd.y)) + pb;
            if (s > mrun) {
                float c = __expf(mrun - s);
                mrun = s;
                l *= c;
                ull cc2 = f2pack(c, c);
#pragma unroll
                for (int t = 0; t < 16; t++) acc2[t] = fmul2(acc2[t], cc2);
            }
            float p = __expf(s - mrun);
            l += p;
            ull pp2 = f2pack(p, p);
            const ulonglong2* vp2 = (const ulonglong2*)(vbase + j * 36);
#pragma unroll
            for (int t = 0; t < 8; t++) {
                ulonglong2 vv = vp2[t];
                acc2[2 * t]     = ffma2(pp2, vv.x, acc2[2 * t]);
                acc2[2 * t + 1] = ffma2(pp2, vv.y, acc2[2 * t + 1]);
            }
        }
        float inv = 1.f / l;
        size_t obase = (((size_t)(b * NWIN + n) * WSZ) + i) * CDIM + hh * DHH;
#pragma unroll
        for (int t = 0; t < 8; t++) {
            float2 p0 = f2unpack(acc2[2 * t]);
            float2 p1 = f2unpack(acc2[2 * t + 1]);
            __nv_bfloat16 h4[4];
            __nv_bfloat16 l4[4];
            split1(p0.x * inv, h4[0], l4[0]);
            split1(p0.y * inv, h4[1], l4[1]);
            split1(p1.x * inv, h4[2], l4[2]);
            split1(p1.y * inv, h4[3], l4[3]);
            *(uint2*)(g_ahi + obase + t * 4) = *(uint2*)h4;
            *(uint2*)(g_alo + obase + t * 4) = *(uint2*)l4;
        }
    } else {
        // ---------------- attn2: cross-window, seq=256 ----------------
        const int m = blockIdx.x;
        const int i = tid;

        float* ks = sm;                   // [128][36]
        float* vs = sm + 128 * 36;

        int h = ((i >> 4) << 3) + (m >> 3);
        int w = ((i & 15) << 3) + (m & 7);
        size_t grow = ((size_t)b << 14) + (h << 7) + w;

        ull qr2[16];
        {
            const ulonglong2* qp = (const ulonglong2*)(g_q + grow * 256 + 128 + hh * DHH);
#pragma unroll
            for (int d4 = 0; d4 < 8; d4++) {
                ulonglong2 q4 = qp[d4];
                qr2[2 * d4]     = q4.x;
                qr2[2 * d4 + 1] = q4.y;
            }
        }

        const float* pos = g_pos2t + hh * NWIN * NWIN;
        float mrun = -INFINITY;
        float l = 0.f;
        ull acc2[16];
#pragma unroll
        for (int t = 0; t < 16; t++) acc2[t] = 0ULL;

        for (int jc = 0; jc < NWIN; jc += 128) {
            __syncthreads();
            {
                int t = tid;
                int r = t & 127;
                int jw = jc + r;
                int hK = ((jw >> 4) << 3) + (m >> 3);
                int wK = ((jw & 15) << 3) + (m & 7);
                size_t gk = ((size_t)b << 14) + (hK << 7) + wK;
                if (t < 128) {
                    const float4* kp = (const float4*)(g_kv + gk * 512 + 128 + hh * DHH);
#pragma unroll
                    for (int d4 = 0; d4 < 8; d4++) *(float4*)(ks + r * 36 + d4 * 4) = kp[d4];
                } else {
                    const float4* vp = (const float4*)(g_kv + gk * 512 + 384 + hh * DHH);
#pragma unroll
                    for (int d4 = 0; d4 < 8; d4++) *(float4*)(vs + r * 36 + d4 * 4) = vp[d4];
                }
            }
            __syncthreads();

#pragma unroll 2
            for (int jj = 0; jj < 128; jj++) {
                float pb = pos[(jc + jj) * NWIN + i];
                const ulonglong2* kp2 = (const ulonglong2*)(ks + jj * 36);
                ull sA = 0ULL;
                ull sB = 0ULL;
                ull sC = 0ULL;
                ull sD = 0ULL;
#pragma unroll
                for (int t = 0; t < 4; t++) {
                    ulonglong2 k0 = kp2[t];
                    ulonglong2 k1 = kp2[t + 4];
                    sA = ffma2(qr2[2 * t],     k0.x, sA);
                    sB = ffma2(qr2[2 * t + 1], k0.y, sB);
                    sC = ffma2(qr2[2 * t + 8], k1.x, sC);
                    sD = ffma2(qr2[2 * t + 9], k1.y, sD);
                }
                float2 a = f2unpack(sA);
                float2 bb = f2unpack(sB);
                float2 cc = f2unpack(sC);
                float2 dd = f2unpack(sD);
                float s = ((a.x + a.y) + (bb.x + bb.y)) + ((cc.x + cc.y) + (dd.x + dd.y)) + pb;
                if (s > mrun) {
                    float c = __expf(mrun - s);
                    mrun = s;
                    l *= c;
                    ull cc2 = f2pack(c, c);
#pragma unroll
                    for (int t = 0; t < 16; t++) acc2[t] = fmul2(acc2[t], cc2);
                }
                float p = __expf(s - mrun);
                l += p;
                ull pp2 = f2pack(p, p);
                const ulonglong2* vp2 = (const ulonglong2*)(vs + jj * 36);
#pragma unroll
                for (int t = 0; t < 8; t++) {
                    ulonglong2 vv = vp2[t];
                    acc2[2 * t]     = ffma2(pp2, vv.x, acc2[2 * t]);
                    acc2[2 * t + 1] = ffma2(pp2, vv.y, acc2[2 * t + 1]);
                }
            }
        }
        float inv = 1.f / l;
        size_t obase = (((size_t)(b * NWIN + i) * WSZ) + m) * CDIM + 128 + hh * DHH;
#pragma unroll
        for (int t = 0; t < 8; t++) {
            float2 p0 = f2unpack(acc2[2 * t]);
            float2 p1 = f2unpack(acc2[2 * t + 1]);
            __nv_bfloat16 h4[4];
            __nv_bfloat16 l4[4];
            split1(p0.x * inv, h4[0], l4[0]);
            split1(p0.y * inv, h4[1], l4[1]);
            split1(p1.x * inv, h4[2], l4[2]);
            split1(p1.y * inv, h4[3], l4[3]);
            *(uint2*)(g_ahi + obase + t * 4) = *(uint2*)h4;
            *(uint2*)(g_alo + obase + t * 4) = *(uint2*)l4;
        }
    }
}

// ---------------------------------------------------------------------------
extern "C" void kernel_launch(void* const* d_in, const int* in_sizes, int n_in,
                              void* d_out, int out_size) {
    const float* x   = (const float*)d_in[0];
    const float* Wq  = (const float*)d_in[1];
    const float* Wkv = (const float*)d_in[2];
    const float* Wo  = (const float*)d_in[3];
    const float* bo  = (const float*)d_in[4];
    const float* p1  = (const float*)d_in[5];
    const float* p2  = (const float*)d_in[6];
    float* out = (float*)d_out;

    cudaFuncSetAttribute(attn_fused, cudaFuncAttributeMaxDynamicSharedMemorySize, AT_SMEM);

    prep_kernel<<<768, 256>>>(p1, p2, Wq, Wkv, Wo);
    split_x<<<2048, 256>>>(x);
    gemm_wmma<<<dim3(6, 512), 256>>>(0, (float*)0, (const float*)0);
    attn_fused<<<dim3(128, 4, 4), 256, AT_SMEM>>>();
    gemm_wmma<<<dim3(2, 512), 256>>>(1, out, bo);
}

// round 12
// speedup vs baseline: 1.2436x; 1.0059x over previous
#include <cuda_runtime.h>
#include <cuda_bf16.h>
#include <mma.h>
#include <math.h>

using namespace nvcuda;

#define NB    4
#define SS    128
#define CDIM  256
#define NHH   4
#define DHH   32
#define NWIN  256
#define WSZ   64
#define MTOT  (NB*SS*SS)
#define NQKV  768
#define QSCALE 0.17677669529663687f

typedef unsigned long long ull;

// ---------------- scratch ----------------
__device__ float g_q  [MTOT * CDIM];
__device__ float g_kv [MTOT * 2 * CDIM];
__device__ __nv_bfloat16 g_xhi[MTOT * CDIM];
__device__ __nv_bfloat16 g_xlo[MTOT * CDIM];
__device__ __nv_bfloat16 g_ahi[MTOT * CDIM];
__device__ __nv_bfloat16 g_alo[MTOT * CDIM];
__device__ __nv_bfloat16 g_whi[CDIM * NQKV];
__device__ __nv_bfloat16 g_wlo[CDIM * NQKV];
__device__ __nv_bfloat16 g_wohi[CDIM * CDIM];
__device__ __nv_bfloat16 g_wolo[CDIM * CDIM];
__device__ float g_pos1t[NHH * WSZ * WSZ];
__device__ float g_pos2t[NHH * NWIN * NWIN];

// ---------------- helpers (no braces inside asm strings) ----------------
union F2U {
    float2 f;
    ull u;
};
__device__ __forceinline__ ull f2pack(float x, float y) {
    F2U t; t.f = make_float2(x, y); return t.u;
}
__device__ __forceinline__ float2 f2unpack(ull v) {
    F2U t; t.u = v; return t.f;
}
__device__ __forceinline__ ull ffma2(ull a, ull b, ull c) {
    ull d;
    asm("fma.rn.f32x2 %0,%1,%2,%3;" : "=l"(d) : "l"(a), "l"(b), "l"(c));
    return d;
}
__device__ __forceinline__ ull fmul2(ull a, ull b) {
    ull d;
    asm("mul.rn.f32x2 %0,%1,%2;" : "=l"(d) : "l"(a), "l"(b));
    return d;
}
__device__ __forceinline__ void split1(float x, __nv_bfloat16& h, __nv_bfloat16& l) {
    h = __float2bfloat16(x);
    l = __float2bfloat16(x - __bfloat162float(h));
}
__device__ __forceinline__ void cpasync16(void* s, const void* g) {
    unsigned saddr = (unsigned)__cvta_generic_to_shared(s);
    asm volatile("cp.async.cg.shared.global [%0], [%1], 16;" :: "r"(saddr), "l"(g));
}
__device__ __forceinline__ void cpcommit() {
    asm volatile("cp.async.commit_group;");
}
__device__ __forceinline__ void cpwait0() {
    asm volatile("cp.async.wait_group 0;");
}
__device__ __forceinline__ void cpwait1() {
    asm volatile("cp.async.wait_group 1;");
}

// ---------------- merged prep: pos transposes + weight splits ----------------
__global__ void prep_kernel(const float* __restrict__ p1,
                            const float* __restrict__ p2,
                            const float* __restrict__ Wq,
                            const float* __restrict__ Wkv,
                            const float* __restrict__ Wo) {
    int idx = blockIdx.x * blockDim.x + threadIdx.x;
    int stride = gridDim.x * blockDim.x;
    for (int i = idx; i < NHH * WSZ * WSZ; i += stride) {
        int hh = i / (WSZ * WSZ);
        int rem = i - hh * WSZ * WSZ;
        int r = rem / WSZ;
        int c = rem % WSZ;
        g_pos1t[(hh * WSZ + c) * WSZ + r] = p1[i];
    }
    for (int i = idx; i < NHH * NWIN * NWIN; i += stride) {
        int hh = i / (NWIN * NWIN);
        int rem = i - hh * NWIN * NWIN;
        int r = rem / NWIN;
        int c = rem % NWIN;
        g_pos2t[(hh * NWIN + c) * NWIN + r] = p2[i];
    }
    for (int i = idx; i < CDIM * CDIM; i += stride) {
        split1(Wo[i], g_wohi[i], g_wolo[i]);
    }
    for (int i = idx; i < CDIM * NQKV; i += stride) {
        int k = i / NQKV;
        int c = i % NQKV;
        float v = (c < 256) ? Wq[k * 256 + c] : Wkv[k * 512 + (c - 256)];
        split1(v, g_whi[i], g_wlo[i]);
    }
}

// ---------------- x split ----------------
__global__ void split_x(const float* __restrict__ src) {
    int idx = blockIdx.x * blockDim.x + threadIdx.x;
    int stride = gridDim.x * blockDim.x;
    const int n4 = MTOT * CDIM / 4;
    for (int i = idx; i < n4; i += stride) {
        float4 v = ((const float4*)src)[i];
        __nv_bfloat16 h4[4];
        __nv_bfloat16 l4[4];
        split1(v.x, h4[0], l4[0]);
        split1(v.y, h4[1], l4[1]);
        split1(v.z, h4[2], l4[2]);
        split1(v.w, h4[3], l4[3]);
        ((uint2*)g_xhi)[i] = *(uint2*)h4;
        ((uint2*)g_xlo)[i] = *(uint2*)l4;
    }
}

// ---------------- WMMA split-bf16 GEMM, cp.async double-buffered ------------
__device__ __forceinline__ int remap_row(int row) {
    int b = row >> 14;
    int n = (row >> 6) & 255;
    int m = row & 63;
    int h = ((n >> 4) << 3) + (m >> 3);
    int w = ((n & 15) << 3) + (m & 7);
    return (b << 14) + (h << 7) + w;
}

__global__ __launch_bounds__(256) void gemm_wmma(
    int mode, float* __restrict__ outp, const float* __restrict__ bo)
{
    const int Ntot = mode ? 256 : NQKV;
    const __nv_bfloat16* __restrict__ Ahi = mode ? g_ahi : g_xhi;
    const __nv_bfloat16* __restrict__ Alo = mode ? g_alo : g_xlo;
    const __nv_bfloat16* __restrict__ Bhi = mode ? g_wohi : g_whi;
    const __nv_bfloat16* __restrict__ Blo = mode ? g_wolo : g_wlo;

    __shared__ __align__(32) __nv_bfloat16 As[2][2][128][24];
    __shared__ __align__(32) __nv_bfloat16 Bs[2][2][16][136];

    const int tid = threadIdx.x;
    const int wid = tid >> 5;
    const int lane = tid & 31;
    const int nb0 = blockIdx.x * 128;
    const int mrow0 = blockIdx.y * 128;
    const int m0w = (wid & 3) * 32;
    const int n0w = (wid >> 2) * 64;

    wmma::fragment<wmma::accumulator, 16, 16, 16, float> cfrag[2][4];
#pragma unroll
    for (int mi = 0; mi < 2; mi++) {
#pragma unroll
        for (int ni = 0; ni < 4; ni++) {
            wmma::fill_fragment(cfrag[mi][ni], 0.0f);
        }
    }

    const int arow = tid >> 1;
    const int acol8 = (tid & 1) * 8;
    const int bkr = tid >> 4;
    const int bnc8 = (tid & 15) * 8;

    {
        cpasync16(&As[0][0][arow][acol8],
                  Ahi + (size_t)(mrow0 + arow) * 256 + acol8);
        cpasync16(&As[0][1][arow][acol8],
                  Alo + (size_t)(mrow0 + arow) * 256 + acol8);
        cpasync16(&Bs[0][0][bkr][bnc8],
                  Bhi + (size_t)(bkr) * Ntot + nb0 + bnc8);
        cpasync16(&Bs[0][1][bkr][bnc8],
                  Blo + (size_t)(bkr) * Ntot + nb0 + bnc8);
        cpcommit();
    }

    const int NT = 256 / 16;
    for (int t = 0; t < NT; t++) {
        int buf = t & 1;
        if (t + 1 < NT) {
            int kn = (t + 1) * 16;
            cpasync16(&As[1 - buf][0][arow][acol8],
                      Ahi + (size_t)(mrow0 + arow) * 256 + kn + acol8);
            cpasync16(&As[1 - buf][1][arow][acol8],
                      Alo + (size_t)(mrow0 + arow) * 256 + kn + acol8);
            cpasync16(&Bs[1 - buf][0][bkr][bnc8],
                      Bhi + (size_t)(kn + bkr) * Ntot + nb0 + bnc8);
            cpasync16(&Bs[1 - buf][1][bkr][bnc8],
                      Blo + (size_t)(kn + bkr) * Ntot + nb0 + bnc8);
            cpcommit();
            cpwait1();
        } else {
            cpwait0();
        }
        __syncthreads();

        wmma::fragment<wmma::matrix_a, 16, 16, 16, __nv_bfloat16, wmma::row_major> afh[2];
        wmma::fragment<wmma::matrix_a, 16, 16, 16, __nv_bfloat16, wmma::row_major> afl[2];
        wmma::load_matrix_sync(afh[0], &As[buf][0][m0w][0], 24);
        wmma::load_matrix_sync(afh[1], &As[buf][0][m0w + 16][0], 24);
        wmma::load_matrix_sync(afl[0], &As[buf][1][m0w][0], 24);
        wmma::load_matrix_sync(afl[1], &As[buf][1][m0w + 16][0], 24);
#pragma unroll
        for (int ni = 0; ni < 4; ni++) {
            wmma::fragment<wmma::matrix_b, 16, 16, 16, __nv_bfloat16, wmma::row_major> bfh;
            wmma::fragment<wmma::matrix_b, 16, 16, 16, __nv_bfloat16, wmma::row_major> bfl;
            wmma::load_matrix_sync(bfh, &Bs[buf][0][0][n0w + ni * 16], 136);
            wmma::load_matrix_sync(bfl, &Bs[buf][1][0][n0w + ni * 16], 136);
#pragma unroll
            for (int mi = 0; mi < 2; mi++) {
                wmma::mma_sync(cfrag[mi][ni], afh[mi], bfh, cfrag[mi][ni]);
                wmma::mma_sync(cfrag[mi][ni], afh[mi], bfl, cfrag[mi][ni]);
                wmma::mma_sync(cfrag[mi][ni], afl[mi], bfh, cfrag[mi][ni]);
            }
        }
        __syncthreads();
    }

    if (mode == 0) {
#pragma unroll
        for (int mi = 0; mi < 2; mi++) {
#pragma unroll
            for (int ni = 0; ni < 4; ni++) {
                int row = mrow0 + m0w + mi * 16;
                int col = nb0 + n0w + ni * 16;
                if (col < 256) {
#pragma unroll
                    for (int e = 0; e < cfrag[mi][ni].num_elements; e++) {
                        cfrag[mi][ni].x[e] *= QSCALE;
                    }
                    wmma::store_matrix_sync(g_q + (size_t)row * 256 + col,
                                            cfrag[mi][ni], 256, wmma::mem_row_major);
                } else {
                    wmma::store_matrix_sync(g_kv + (size_t)row * 512 + (col - 256),
                                            cfrag[mi][ni], 512, wmma::mem_row_major);
                }
            }
        }
    } else {
        float* stg = (float*)&As[0][0][0][0];
        float* mystg = stg + wid * 256;
#pragma unroll
        for (int mi = 0; mi < 2; mi++) {
#pragma unroll
            for (int ni = 0; ni < 4; ni++) {
                wmma::store_matrix_sync(mystg, cfrag[mi][ni], 16, wmma::mem_row_major);
                __syncwarp();
                int row0 = mrow0 + m0w + mi * 16;
                int col0 = nb0 + n0w + ni * 16;
#pragma unroll
                for (int e = 0; e < 8; e++) {
                    int idx = lane * 8 + e;
                    int r = idx >> 4;
                    int c = idx & 15;
                    int grow = remap_row(row0 + r);
                    outp[(size_t)grow * 256 + col0 + c] = mystg[r * 16 + c] + bo[col0 + c];
                }
                __syncwarp();
            }
        }
    }
}

// ---------------- attention branch 1 (within-window, seq=64) ----------------
__global__ __launch_bounds__(64) void attn1_kernel() {
    int n  = blockIdx.x;
    int hh = blockIdx.y;
    int b  = blockIdx.z;
    int i  = threadIdx.x;

    __shared__ float ks[WSZ][36];
    __shared__ float vs[WSZ][36];

    int h = ((n >> 4) << 3) + (i >> 3);
    int w = ((n & 15) << 3) + (i & 7);
    size_t grow = ((size_t)b << 14) + (h << 7) + w;

    {
        const float4* kp = (const float4*)(g_kv + grow * 512 + hh * DHH);
        const float4* vp = (const float4*)(g_kv + grow * 512 + 256 + hh * DHH);
#pragma unroll
        for (int d4 = 0; d4 < 8; d4++) {
            *(float4*)(&ks[i][d4 * 4]) = kp[d4];
            *(float4*)(&vs[i][d4 * 4]) = vp[d4];
        }
    }
    ull qr2[16];
    {
        const ulonglong2* qp = (const ulonglong2*)(g_q + grow * 256 + hh * DHH);
#pragma unroll
        for (int d4 = 0; d4 < 8; d4++) {
            ulonglong2 q4 = qp[d4];
            qr2[2 * d4]     = q4.x;
            qr2[2 * d4 + 1] = q4.y;
        }
    }
    __syncthreads();

    const float* pos = g_pos1t + hh * WSZ * WSZ;
    float mrun = -INFINITY;
    float l = 0.f;
    ull acc2[16];
#pragma unroll
    for (int t = 0; t < 16; t++) acc2[t] = 0ULL;

    // software-pipelined pos prefetch (hide L2 latency)
    float pb_next = pos[i];

#pragma unroll 2
    for (int j = 0; j < WSZ; j++) {
        float pb = pb_next;
        int jn = (j + 1 < WSZ) ? (j + 1) : j;
        pb_next = pos[jn * WSZ + i];
        const ulonglong2* kp2 = (const ulonglong2*)(&ks[j][0]);
        ull sA = 0ULL;
        ull sB = 0ULL;
        ull sC = 0ULL;
        ull sD = 0ULL;
#pragma unroll
        for (int t = 0; t < 4; t++) {
            ulonglong2 k0 = kp2[t];
            ulonglong2 k1 = kp2[t + 4];
            sA = ffma2(qr2[2 * t],     k0.x, sA);
            sB = ffma2(qr2[2 * t + 1], k0.y, sB);
            sC = ffma2(qr2[2 * t + 8], k1.x, sC);
            sD = ffma2(qr2[2 * t + 9], k1.y, sD);
        }
        float2 a = f2unpack(sA);
        float2 bb = f2unpack(sB);
        float2 cc = f2unpack(sC);
        float2 dd = f2unpack(sD);
        float s = ((a.x + a.y) + (bb.x + bb.y)) + ((cc.x + cc.y) + (dd.x + dd.y)) + pb;
        if (s > mrun) {
            float c = __expf(mrun - s);
            mrun = s;
            l *= c;
            ull cc2 = f2pack(c, c);
#pragma unroll
            for (int t = 0; t < 16; t++) acc2[t] = fmul2(acc2[t], cc2);
        }
        float p = __expf(s - mrun);
        l += p;
        ull pp2 = f2pack(p, p);
        const ulonglong2* vp2 = (const ulonglong2*)(&vs[j][0]);
#pragma unroll
        for (int t = 0; t < 8; t++) {
            ulonglong2 vv = vp2[t];
            acc2[2 * t]     = ffma2(pp2, vv.x, acc2[2 * t]);
            acc2[2 * t + 1] = ffma2(pp2, vv.y, acc2[2 * t + 1]);
        }
    }
    float inv = 1.f / l;
    size_t obase = (((size_t)(b * NWIN + n) * WSZ) + i) * CDIM + hh * DHH;
#pragma unroll
    for (int t = 0; t < 8; t++) {
        float2 p0 = f2unpack(acc2[2 * t]);
        float2 p1 = f2unpack(acc2[2 * t + 1]);
        __nv_bfloat16 h4[4];
        __nv_bfloat16 l4[4];
        split1(p0.x * inv, h4[0], l4[0]);
        split1(p0.y * inv, h4[1], l4[1]);
        split1(p1.x * inv, h4[2], l4[2]);
        split1(p1.y * inv, h4[3], l4[3]);
        *(uint2*)(g_ahi + obase + t * 4) = *(uint2*)h4;
        *(uint2*)(g_alo + obase + t * 4) = *(uint2*)l4;
    }
}

// ---------------- attention branch 2 (cross-window, seq=256) ----------------
__global__ __launch_bounds__(256) void attn2_kernel() {
    int m  = blockIdx.x;
    int hh = blockIdx.y;
    int b  = blockIdx.z;
    int i  = threadIdx.x;

    __shared__ float ks[128][36];
    __shared__ float vs[128][36];

    int h = ((i >> 4) << 3) + (m >> 3);
    int w = ((i & 15) << 3) + (m & 7);
    size_t grow = ((size_t)b << 14) + (h << 7) + w;

    ull qr2[16];
    {
        const ulonglong2* qp = (const ulonglong2*)(g_q + grow * 256 + 128 + hh * DHH);
#pragma unroll
        for (int d4 = 0; d4 < 8; d4++) {
            ulonglong2 q4 = qp[d4];
            qr2[2 * d4]     = q4.x;
            qr2[2 * d4 + 1] = q4.y;
        }
    }

    const float* pos = g_pos2t + hh * NWIN * NWIN;
    float mrun = -INFINITY;
    float l = 0.f;
    ull acc2[16];
#pragma unroll
    for (int t = 0; t < 16; t++) acc2[t] = 0ULL;

    // software-pipelined pos prefetch across the whole 256-key range
    float pb_next = pos[i];

    for (int jc = 0; jc < NWIN; jc += 128) {
        __syncthreads();
        {
            int t = threadIdx.x;
            int r = t & 127;
            int jw = jc + r;
            int hK = ((jw >> 4) << 3) + (m >> 3);
            int wK = ((jw & 15) << 3) + (m & 7);
            size_t gk = ((size_t)b << 14) + (hK << 7) + wK;
            if (t < 128) {
                const float4* kp = (const float4*)(g_kv + gk * 512 + 128 + hh * DHH);
#pragma unroll
                for (int d4 = 0; d4 < 8; d4++) *(float4*)(&ks[r][d4 * 4]) = kp[d4];
            } else {
                const float4* vp = (const float4*)(g_kv + gk * 512 + 384 + hh * DHH);
#pragma unroll
                for (int d4 = 0; d4 < 8; d4++) *(float4*)(&vs[r][d4 * 4]) = vp[d4];
            }
        }
        __syncthreads();

#pragma unroll 2
        for (int jj = 0; jj < 128; jj++) {
            float pb = pb_next;
            int j = jc + jj;
            int jn = (j + 1 < NWIN) ? (j + 1) : j;
            pb_next = pos[jn * NWIN + i];
            const ulonglong2* kp2 = (const ulonglong2*)(&ks[jj][0]);
            ull sA = 0ULL;
            ull sB = 0ULL;
            ull sC = 0ULL;
            ull sD = 0ULL;
#pragma unroll
            for (int t = 0; t < 4; t++) {
                ulonglong2 k0 = kp2[t];
                ulonglong2 k1 = kp2[t + 4];
                sA = ffma2(qr2[2 * t],     k0.x, sA);
                sB = ffma2(qr2[2 * t + 1], k0.y, sB);
                sC = ffma2(qr2[2 * t + 8], k1.x, sC);
                sD = ffma2(qr2[2 * t + 9], k1.y, sD);
            }
            float2 a = f2unpack(sA);
            float2 bb = f2unpack(sB);
            float2 cc = f2unpack(sC);
            float2 dd = f2unpack(sD);
            float s = ((a.x + a.y) + (bb.x + bb.y)) + ((cc.x + cc.y) + (dd.x + dd.y)) + pb;
            if (s > mrun) {
                float c = __expf(mrun - s);
                mrun = s;
                l *= c;
                ull cc2 = f2pack(c, c);
#pragma unroll
                for (int t = 0; t < 16; t++) acc2[t] = fmul2(acc2[t], cc2);
            }
            float p = __expf(s - mrun);
            l += p;
            ull pp2 = f2pack(p, p);
            const ulonglong2* vp2 = (const ulonglong2*)(&vs[jj][0]);
#pragma unroll
            for (int t = 0; t < 8; t++) {
                ulonglong2 vv = vp2[t];
                acc2[2 * t]     = ffma2(pp2, vv.x, acc2[2 * t]);
                acc2[2 * t + 1] = ffma2(pp2, vv.y, acc2[2 * t + 1]);
            }
        }
    }
    float inv = 1.f / l;
    size_t obase = (((size_t)(b * NWIN + i) * WSZ) + m) * CDIM + 128 + hh * DHH;
#pragma unroll
    for (int t = 0; t < 8; t++) {
        float2 p0 = f2unpack(acc2[2 * t]);
        float2 p1 = f2unpack(acc2[2 * t + 1]);
        __nv_bfloat16 h4[4];
        __nv_bfloat16 l4[4];
        split1(p0.x * inv, h4[0], l4[0]);
        split1(p0.y * inv, h4[1], l4[1]);
        split1(p1.x * inv, h4[2], l4[2]);
        split1(p1.y * inv, h4[3], l4[3]);
        *(uint2*)(g_ahi + obase + t * 4) = *(uint2*)h4;
        *(uint2*)(g_alo + obase + t * 4) = *(uint2*)l4;
    }
}

// ---------------------------------------------------------------------------
extern "C" void kernel_launch(void* const* d_in, const int* in_sizes, int n_in,
                              void* d_out, int out_size) {
    const float* x   = (const float*)d_in[0];
    const float* Wq  = (const float*)d_in[1];
    const float* Wkv = (const float*)d_in[2];
    const float* Wo  = (const float*)d_in[3];
    const float* bo  = (const float*)d_in[4];
    const float* p1  = (const float*)d_in[5];
    const float* p2  = (const float*)d_in[6];
    float* out = (float*)d_out;

    prep_kernel<<<768, 256>>>(p1, p2, Wq, Wkv, Wo);
    split_x<<<2048, 256>>>(x);
    gemm_wmma<<<dim3(6, 512), 256>>>(0, (float*)0, (const float*)0);
    attn1_kernel<<<dim3(256, 4, 4), 64>>>();
    attn2_kernel<<<dim3(64, 4, 4), 256>>>();
    gemm_wmma<<<dim3(2, 512), 256>>>(1, out, bo);
}